// round 1
// baseline (speedup 1.0000x reference)
#include <cuda_runtime.h>
#include <math.h>

#define NTOK 4096
#define DIM  1024
#define HID  4096
#define NEXP 8
#define TOPK 2
#define NSLOT (NTOK * TOPK)

#define BM 64
#define BN 64
#define BK 16

// -------- static scratch (no allocations allowed) --------
__device__ float g_hbuf[(size_t)NSLOT * HID];   // 134 MB hidden activations
__device__ int   g_list_tok[NSLOT];
__device__ float g_list_wgt[NSLOT];
__device__ int   g_counts[NEXP];
__device__ int   g_offsets[NEXP];
__device__ int   g_cursor[NEXP];
__device__ int   g_tok_e[NTOK * TOPK];
__device__ float g_tok_w[NTOK * TOPK];

__device__ __forceinline__ float gelu_exact(float v) {
    return 0.5f * v * (1.0f + erff(v * 0.70710678118654752f));
}

// -------- zero output + counters --------
__global__ void zero_kernel(float* __restrict__ out, int n) {
    int i = blockIdx.x * blockDim.x + threadIdx.x;
    if (i < n) out[i] = 0.0f;
    if (i < NEXP) { g_counts[i] = 0; g_cursor[i] = 0; }
}

// -------- gating: logits -> softmax -> top2 -> normalized weights --------
__global__ void gate_kernel(const float* __restrict__ x,
                            const float* __restrict__ gw,
                            const float* __restrict__ gb) {
    int warp = (blockIdx.x * blockDim.x + threadIdx.x) >> 5;
    int lane = threadIdx.x & 31;
    if (warp >= NTOK) return;
    const float* xr = x + (size_t)warp * DIM;

    float acc[NEXP];
#pragma unroll
    for (int e = 0; e < NEXP; e++) acc[e] = 0.0f;

    for (int d = lane; d < DIM; d += 32) {
        float xv = xr[d];
        const float* g = gw + d * NEXP;
#pragma unroll
        for (int e = 0; e < NEXP; e++) acc[e] += xv * g[e];
    }
#pragma unroll
    for (int e = 0; e < NEXP; e++) {
#pragma unroll
        for (int o = 16; o > 0; o >>= 1)
            acc[e] += __shfl_xor_sync(0xffffffffu, acc[e], o);
    }

    if (lane == 0) {
        float l[NEXP];
        float mx = -1e30f;
#pragma unroll
        for (int e = 0; e < NEXP; e++) {
            l[e] = acc[e] + gb[e];
            mx = fmaxf(mx, l[e]);
        }
        float g[NEXP];
        float Z = 0.0f;
#pragma unroll
        for (int e = 0; e < NEXP; e++) { g[e] = expf(l[e] - mx); Z += g[e]; }

        // top-2 (first index wins ties, matching lax.top_k)
        int b1 = 0;
#pragma unroll
        for (int e = 1; e < NEXP; e++) if (g[e] > g[b1]) b1 = e;
        int b2 = -1;
#pragma unroll
        for (int e = 0; e < NEXP; e++) {
            if (e == b1) continue;
            if (b2 < 0 || g[e] > g[b2]) b2 = e;
        }
        float v1 = g[b1] / Z;
        float v2 = g[b2] / Z;
        float s = v1 + v2 + 1e-9f;
        g_tok_e[warp * 2 + 0] = b1;  g_tok_w[warp * 2 + 0] = v1 / s;
        g_tok_e[warp * 2 + 1] = b2;  g_tok_w[warp * 2 + 1] = v2 / s;
        atomicAdd(&g_counts[b1], 1);
        atomicAdd(&g_counts[b2], 1);
    }
}

// -------- exclusive prefix over expert counts --------
__global__ void prefix_kernel() {
    int s = 0;
    for (int e = 0; e < NEXP; e++) { g_offsets[e] = s; s += g_counts[e]; }
}

// -------- scatter tokens into per-expert contiguous lists --------
__global__ void scatter_kernel() {
    int t = blockIdx.x * blockDim.x + threadIdx.x;
    if (t >= NTOK) return;
#pragma unroll
    for (int k = 0; k < TOPK; k++) {
        int e = g_tok_e[t * 2 + k];
        int pos = atomicAdd(&g_cursor[e], 1);
        g_list_tok[g_offsets[e] + pos] = t;
        g_list_wgt[g_offsets[e] + pos] = g_tok_w[t * 2 + k];
    }
}

// -------- GEMM1: h = gelu(x[toks] @ w1[e] + b1[e]) -> g_hbuf --------
__global__ void gemm1_kernel(const float* __restrict__ x,
                             const float* __restrict__ w1,
                             const float* __restrict__ b1) {
    int e = blockIdx.z;
    int cnt = g_counts[e];
    int row0 = blockIdx.y * BM;
    if (row0 >= cnt) return;
    int col0 = blockIdx.x * BN;
    int off = g_offsets[e];
    const float* W = w1 + (size_t)e * DIM * HID;

    __shared__ float As[BK][BM + 4];
    __shared__ float Bs[BK][BN + 4];

    int tid = threadIdx.x;
    int am = tid >> 2;
    int ak = (tid & 3) * 4;
    int arow = row0 + am;
    int tok = g_list_tok[off + min(arow, cnt - 1)];
    const float* Arow = x + (size_t)tok * DIM;

    int bk = tid >> 4;
    int bn = (tid & 15) * 4;
    int ty = tid >> 4;
    int tx = tid & 15;

    float c[4][4] = {};

    for (int k0 = 0; k0 < DIM; k0 += BK) {
        float4 av = *(const float4*)(Arow + k0 + ak);
        As[ak + 0][am] = av.x; As[ak + 1][am] = av.y;
        As[ak + 2][am] = av.z; As[ak + 3][am] = av.w;
        *(float4*)&Bs[bk][bn] =
            *(const float4*)(W + (size_t)(k0 + bk) * HID + col0 + bn);
        __syncthreads();
#pragma unroll
        for (int k = 0; k < BK; k++) {
            float4 a = *(const float4*)&As[k][ty * 4];
            float4 b = *(const float4*)&Bs[k][tx * 4];
            c[0][0] += a.x * b.x; c[0][1] += a.x * b.y; c[0][2] += a.x * b.z; c[0][3] += a.x * b.w;
            c[1][0] += a.y * b.x; c[1][1] += a.y * b.y; c[1][2] += a.y * b.z; c[1][3] += a.y * b.w;
            c[2][0] += a.z * b.x; c[2][1] += a.z * b.y; c[2][2] += a.z * b.z; c[2][3] += a.z * b.w;
            c[3][0] += a.w * b.x; c[3][1] += a.w * b.y; c[3][2] += a.w * b.z; c[3][3] += a.w * b.w;
        }
        __syncthreads();
    }

#pragma unroll
    for (int i = 0; i < 4; i++) {
        int r = row0 + ty * 4 + i;
        if (r >= cnt) continue;
        size_t slot = (size_t)(off + r);
#pragma unroll
        for (int j = 0; j < 4; j++) {
            int cc = col0 + tx * 4 + j;
            float v = c[i][j] + b1[e * HID + cc];
            g_hbuf[slot * HID + cc] = gelu_exact(v);
        }
    }
}

// -------- GEMM2: out[tok] += wgt * (h @ w2[e] + b2[e]) --------
__global__ void gemm2_kernel(const float* __restrict__ w2,
                             const float* __restrict__ b2,
                             float* __restrict__ out) {
    int e = blockIdx.z;
    int cnt = g_counts[e];
    int row0 = blockIdx.y * BM;
    if (row0 >= cnt) return;
    int col0 = blockIdx.x * BN;
    int off = g_offsets[e];
    const float* W = w2 + (size_t)e * HID * DIM;

    __shared__ float As[BK][BM + 4];
    __shared__ float Bs[BK][BN + 4];

    int tid = threadIdx.x;
    int am = tid >> 2;
    int ak = (tid & 3) * 4;
    int arow = row0 + am;
    size_t slot_ld = (size_t)(off + min(arow, cnt - 1));
    const float* Arow = g_hbuf + slot_ld * HID;

    int bk = tid >> 4;
    int bn = (tid & 15) * 4;
    int ty = tid >> 4;
    int tx = tid & 15;

    float c[4][4] = {};

    for (int k0 = 0; k0 < HID; k0 += BK) {
        float4 av = *(const float4*)(Arow + k0 + ak);
        As[ak + 0][am] = av.x; As[ak + 1][am] = av.y;
        As[ak + 2][am] = av.z; As[ak + 3][am] = av.w;
        *(float4*)&Bs[bk][bn] =
            *(const float4*)(W + (size_t)(k0 + bk) * DIM + col0 + bn);
        __syncthreads();
#pragma unroll
        for (int k = 0; k < BK; k++) {
            float4 a = *(const float4*)&As[k][ty * 4];
            float4 b = *(const float4*)&Bs[k][tx * 4];
            c[0][0] += a.x * b.x; c[0][1] += a.x * b.y; c[0][2] += a.x * b.z; c[0][3] += a.x * b.w;
            c[1][0] += a.y * b.x; c[1][1] += a.y * b.y; c[1][2] += a.y * b.z; c[1][3] += a.y * b.w;
            c[2][0] += a.z * b.x; c[2][1] += a.z * b.y; c[2][2] += a.z * b.z; c[2][3] += a.z * b.w;
            c[3][0] += a.w * b.x; c[3][1] += a.w * b.y; c[3][2] += a.w * b.z; c[3][3] += a.w * b.w;
        }
        __syncthreads();
    }

#pragma unroll
    for (int i = 0; i < 4; i++) {
        int r = row0 + ty * 4 + i;
        if (r >= cnt) continue;
        int s = off + r;
        int tok = g_list_tok[s];
        float w = g_list_wgt[s];
#pragma unroll
        for (int j = 0; j < 4; j++) {
            int cc = col0 + tx * 4 + j;
            atomicAdd(&out[(size_t)tok * DIM + cc],
                      w * (c[i][j] + b2[e * DIM + cc]));
        }
    }
}

extern "C" void kernel_launch(void* const* d_in, const int* in_sizes, int n_in,
                              void* d_out, int out_size) {
    const float* x  = (const float*)d_in[0];
    const float* gw = (const float*)d_in[1];
    const float* gb = (const float*)d_in[2];
    const float* w1 = (const float*)d_in[3];
    const float* b1 = (const float*)d_in[4];
    const float* w2 = (const float*)d_in[5];
    const float* b2 = (const float*)d_in[6];
    float* out = (float*)d_out;

    zero_kernel<<<(out_size + 255) / 256, 256>>>(out, out_size);
    gate_kernel<<<NTOK / 8, 256>>>(x, gw, gb);
    prefix_kernel<<<1, 1>>>();
    scatter_kernel<<<NTOK / 256, 256>>>();
    gemm1_kernel<<<dim3(HID / BN, NTOK / BM, NEXP), 256>>>(x, w1, b1);
    gemm2_kernel<<<dim3(DIM / BN, NTOK / BM, NEXP), 256>>>(w2, b2, out);
}

// round 5
// speedup vs baseline: 2.6363x; 2.6363x over previous
#include <cuda_runtime.h>
#include <cuda_bf16.h>
#include <math.h>
#include <stdint.h>

#define NTOK 4096
#define DIM  1024
#define HID  4096
#define NEXP 8
#define TOPK 2
#define NSLOT (NTOK * TOPK)
#define MAXMT 72

#define ASTRIDE 80           // 64B row + 16B pad (A tile: 128 rows x 32 bf16)
#define BSTRIDE 272          // 256B row + 16B pad (B tile: 32 k-rows x 128 bf16)
#define ATILE_B (128 * ASTRIDE)          // 10240
#define STAGE_B (ATILE_B + 32 * BSTRIDE) // 18944
#define SMEM_BYTES (1024 + 2 * STAGE_B)  // 38912 < 48KB: no opt-in needed

// ---- static scratch ----
__device__ __align__(128) __nv_bfloat16 g_xh[(size_t)NTOK * DIM];
__device__ __align__(128) __nv_bfloat16 g_xl[(size_t)NTOK * DIM];
__device__ __align__(128) __nv_bfloat16 g_w1h[(size_t)NEXP * DIM * HID];
__device__ __align__(128) __nv_bfloat16 g_w1l[(size_t)NEXP * DIM * HID];
__device__ __align__(128) __nv_bfloat16 g_w2h[(size_t)NEXP * HID * DIM];
__device__ __align__(128) __nv_bfloat16 g_w2l[(size_t)NEXP * HID * DIM];
__device__ __align__(128) __nv_bfloat16 g_hh[(size_t)NSLOT * HID];
__device__ __align__(128) __nv_bfloat16 g_hl[(size_t)NSLOT * HID];
__device__ __align__(128) float g_y[(size_t)NSLOT * DIM];

__device__ int   g_list_tok[NSLOT];
__device__ float g_list_wgt[NSLOT];
__device__ int   g_slot_of[NTOK * TOPK];
__device__ int   g_counts[NEXP];
__device__ int   g_offsets[NEXP];
__device__ int   g_cursor[NEXP];
__device__ int   g_tok_e[NTOK * TOPK];
__device__ float g_tok_w[NTOK * TOPK];
__device__ int   g_tile_e[MAXMT];
__device__ int   g_tile_r0[MAXMT];
__device__ int   g_num_mtiles;

// ===================== helpers =====================
__device__ __forceinline__ uint32_t smem_to_u32(const void* p) {
    uint32_t a;
    asm("{ .reg .u64 t; cvta.to.shared.u64 t, %1; cvt.u32.u64 %0, t; }"
        : "=r"(a) : "l"(p));
    return a;
}
__device__ __forceinline__ void cpa16(uint32_t dst, const void* src) {
    asm volatile("cp.async.cg.shared.global [%0], [%1], 16;"
                 :: "r"(dst), "l"(src));
}
#define CPA_COMMIT() asm volatile("cp.async.commit_group;" ::: "memory")
#define CPA_WAIT1()  asm volatile("cp.async.wait_group 1;" ::: "memory")

__device__ __forceinline__ void ldsm_x4(uint32_t* r, uint32_t addr) {
    asm volatile("ldmatrix.sync.aligned.m8n8.x4.shared.b16 {%0,%1,%2,%3}, [%4];"
        : "=r"(r[0]), "=r"(r[1]), "=r"(r[2]), "=r"(r[3]) : "r"(addr));
}
__device__ __forceinline__ void ldsm_x4_t(uint32_t* r, uint32_t addr) {
    asm volatile("ldmatrix.sync.aligned.m8n8.x4.trans.shared.b16 {%0,%1,%2,%3}, [%4];"
        : "=r"(r[0]), "=r"(r[1]), "=r"(r[2]), "=r"(r[3]) : "r"(addr));
}
__device__ __forceinline__ void mma16816(float* c, const uint32_t* a,
                                         uint32_t b0, uint32_t b1) {
    asm volatile("mma.sync.aligned.m16n8k16.row.col.f32.bf16.bf16.f32 "
        "{%0,%1,%2,%3}, {%4,%5,%6,%7}, {%8,%9}, {%0,%1,%2,%3};"
        : "+f"(c[0]), "+f"(c[1]), "+f"(c[2]), "+f"(c[3])
        : "r"(a[0]), "r"(a[1]), "r"(a[2]), "r"(a[3]), "r"(b0), "r"(b1));
}
__device__ __forceinline__ float gelu_exact(float v) {
    return 0.5f * v * (1.0f + erff(v * 0.70710678118654752f));
}

// ===================== small kernels =====================
__global__ void init_kernel() {
    int i = threadIdx.x;
    if (i < NEXP) { g_counts[i] = 0; g_cursor[i] = 0; }
}

__global__ void gate_kernel(const float* __restrict__ x,
                            const float* __restrict__ gw,
                            const float* __restrict__ gb) {
    int warp = (blockIdx.x * blockDim.x + threadIdx.x) >> 5;
    int lane = threadIdx.x & 31;
    if (warp >= NTOK) return;
    const float* xr = x + (size_t)warp * DIM;
    float acc[NEXP];
#pragma unroll
    for (int e = 0; e < NEXP; e++) acc[e] = 0.0f;
    for (int d = lane; d < DIM; d += 32) {
        float xv = xr[d];
        const float* g = gw + d * NEXP;
#pragma unroll
        for (int e = 0; e < NEXP; e++) acc[e] += xv * g[e];
    }
#pragma unroll
    for (int e = 0; e < NEXP; e++) {
#pragma unroll
        for (int o = 16; o > 0; o >>= 1)
            acc[e] += __shfl_xor_sync(0xffffffffu, acc[e], o);
    }
    if (lane == 0) {
        float l[NEXP], g[NEXP];
        float mx = -1e30f;
#pragma unroll
        for (int e = 0; e < NEXP; e++) { l[e] = acc[e] + gb[e]; mx = fmaxf(mx, l[e]); }
        float Z = 0.0f;
#pragma unroll
        for (int e = 0; e < NEXP; e++) { g[e] = expf(l[e] - mx); Z += g[e]; }
        int b1 = 0;
#pragma unroll
        for (int e = 1; e < NEXP; e++) if (g[e] > g[b1]) b1 = e;
        int b2 = -1;
#pragma unroll
        for (int e = 0; e < NEXP; e++) {
            if (e == b1) continue;
            if (b2 < 0 || g[e] > g[b2]) b2 = e;
        }
        float v1 = g[b1] / Z, v2 = g[b2] / Z;
        float s = v1 + v2 + 1e-9f;
        g_tok_e[warp * 2 + 0] = b1;  g_tok_w[warp * 2 + 0] = v1 / s;
        g_tok_e[warp * 2 + 1] = b2;  g_tok_w[warp * 2 + 1] = v2 / s;
        atomicAdd(&g_counts[b1], 1);
        atomicAdd(&g_counts[b2], 1);
    }
}

__global__ void prefix_kernel() {
    int s = 0, nt = 0;
    for (int e = 0; e < NEXP; e++) {
        g_offsets[e] = s;
        int c = g_counts[e];
        s += c;
        int t = (c + 127) / 128;
        for (int i = 0; i < t; i++) { g_tile_e[nt] = e; g_tile_r0[nt] = i * 128; nt++; }
    }
    g_num_mtiles = nt;
}

__global__ void scatter_kernel() {
    int t = blockIdx.x * blockDim.x + threadIdx.x;
    if (t >= NTOK) return;
#pragma unroll
    for (int k = 0; k < TOPK; k++) {
        int e = g_tok_e[t * 2 + k];
        int pos = atomicAdd(&g_cursor[e], 1);
        int slot = g_offsets[e] + pos;
        g_list_tok[slot] = t;
        g_list_wgt[slot] = g_tok_w[t * 2 + k];
        g_slot_of[t * 2 + k] = slot;
    }
}

// elementwise hi/lo split; destination selected DEVICE-SIDE (passing the
// address of a __device__ array from host code is UB — that was the R3/R4 bug)
__global__ void split_kernel(const float* __restrict__ src, int which, size_t n4) {
    size_t i = (size_t)blockIdx.x * blockDim.x + threadIdx.x;
    if (i >= n4) return;
    __nv_bfloat16 *dh, *dl;
    if (which == 0)      { dh = g_xh;  dl = g_xl;  }
    else if (which == 1) { dh = g_w1h; dl = g_w1l; }
    else                 { dh = g_w2h; dl = g_w2l; }
    float4 v = ((const float4*)src)[i];
    __nv_bfloat16 h0 = __float2bfloat16(v.x), h1 = __float2bfloat16(v.y);
    __nv_bfloat16 h2 = __float2bfloat16(v.z), h3 = __float2bfloat16(v.w);
    __nv_bfloat16 l0 = __float2bfloat16(v.x - __bfloat162float(h0));
    __nv_bfloat16 l1 = __float2bfloat16(v.y - __bfloat162float(h1));
    __nv_bfloat16 l2 = __float2bfloat16(v.z - __bfloat162float(h2));
    __nv_bfloat16 l3 = __float2bfloat16(v.w - __bfloat162float(h3));
    ((__nv_bfloat162*)dh)[i * 2 + 0] = __halves2bfloat162(h0, h1);
    ((__nv_bfloat162*)dh)[i * 2 + 1] = __halves2bfloat162(h2, h3);
    ((__nv_bfloat162*)dl)[i * 2 + 0] = __halves2bfloat162(l0, l1);
    ((__nv_bfloat162*)dl)[i * 2 + 1] = __halves2bfloat162(l2, l3);
}

// ===================== GEMM kernels (mma.sync bf16 x3 split, BK=32, 2-stage) =====================
__global__ __launch_bounds__(256, 2)
void gemm1_mma(const float* __restrict__ b1) {
    int tile = blockIdx.y;
    if (tile >= g_num_mtiles) return;
    int e = g_tile_e[tile], row0 = g_tile_r0[tile];
    int cnt = g_counts[e], off = g_offsets[e];
    int col0 = blockIdx.x * 128;
    extern __shared__ char sm[];
    uint32_t smb = smem_to_u32(sm);
    int tid = threadIdx.x, lane = tid & 31, wid = tid >> 5;
    int* s_row = (int*)sm;
    if (tid < 128) s_row[tid] = g_list_tok[off + min(row0 + tid, max(cnt - 1, 0))];
    __syncthreads();

    const __nv_bfloat16* Bh = g_w1h + (size_t)e * DIM * HID;
    const __nv_bfloat16* Bl = g_w1l + (size_t)e * DIM * HID;

    auto load_chunk = [&](int c, int slot) {
        int ph = c >> 5;                 // 32 k-chunks per phase (DIM/32)
        int kk = (c & 31) << 5;
        const __nv_bfloat16* As = (ph < 2) ? g_xh : g_xl;
        const __nv_bfloat16* Bs = (ph == 1) ? Bl : Bh;
        uint32_t ab = smb + 1024 + slot * STAGE_B;
        uint32_t bb = ab + ATILE_B;
#pragma unroll
        for (int i = 0; i < 2; i++) {    // A: 512 chunks of 16B
            int item = tid + (i << 8);
            int r = item >> 2, ch = item & 3;
            cpa16(ab + r * ASTRIDE + ch * 16,
                  (const char*)(As + (size_t)s_row[r] * DIM + kk) + ch * 16);
        }
#pragma unroll
        for (int i = 0; i < 2; i++) {    // B: 512 chunks of 16B
            int item = tid + (i << 8);
            int r = item >> 4, ch = item & 15;
            cpa16(bb + r * BSTRIDE + ch * 16,
                  (const char*)(Bs + (size_t)(kk + r) * HID + col0) + ch * 16);
        }
    };

    float acc[2][8][4];
#pragma unroll
    for (int a = 0; a < 2; a++)
#pragma unroll
        for (int b = 0; b < 8; b++)
#pragma unroll
            for (int q = 0; q < 4; q++) acc[a][b][q] = 0.0f;

    int m0 = (wid >> 1) * 32;
    int n0w = (wid & 1) * 64;
    uint32_t aoff = (uint32_t)((m0 + (lane & 15)) * ASTRIDE + (lane >> 4) * 16);
    uint32_t boff = (uint32_t)(((((lane >> 3) & 1) << 3) + (lane & 7)) * BSTRIDE +
                               (n0w + (lane >> 4) * 8) * 2);

    load_chunk(0, 0); CPA_COMMIT();
    load_chunk(1, 1); CPA_COMMIT();
    const int NCH = 96;                  // 3 phases x 32
    for (int c = 0; c < NCH; c++) {
        CPA_WAIT1();
        __syncthreads();
        int sl = c & 1;
        uint32_t ab = smb + 1024 + sl * STAGE_B;
        uint32_t bb = ab + ATILE_B;
#pragma unroll
        for (int ks = 0; ks < 2; ks++) {
            uint32_t a0[4], a1[4], bg[4][4];
            ldsm_x4(a0, ab + aoff + ks * 32);
            ldsm_x4(a1, ab + aoff + ks * 32 + 16 * ASTRIDE);
#pragma unroll
            for (int ng = 0; ng < 4; ng++)
                ldsm_x4_t(bg[ng], bb + boff + ks * 16 * BSTRIDE + ng * 32);
#pragma unroll
            for (int nt = 0; nt < 8; nt++) {
                uint32_t b0 = bg[nt >> 1][(nt & 1) * 2];
                uint32_t b1v = bg[nt >> 1][(nt & 1) * 2 + 1];
                mma16816(acc[0][nt], a0, b0, b1v);
                mma16816(acc[1][nt], a1, b0, b1v);
            }
        }
        __syncthreads();
        if (c + 2 < NCH) load_chunk(c + 2, sl);
        CPA_COMMIT();
    }

    int qr = lane >> 2, qc = (lane & 3) * 2;
#pragma unroll
    for (int mt = 0; mt < 2; mt++) {
#pragma unroll
        for (int i = 0; i < 2; i++) {
            int ml = m0 + mt * 16 + qr + i * 8;
            int r = row0 + ml;
            if (r < cnt) {
                size_t sl2 = (size_t)(off + r);
#pragma unroll
                for (int nt = 0; nt < 8; nt++) {
                    int col = col0 + n0w + nt * 8 + qc;
                    float2 bv = *(const float2*)(b1 + (size_t)e * HID + col);
                    float g0 = gelu_exact(acc[mt][nt][i * 2 + 0] + bv.x);
                    float g1 = gelu_exact(acc[mt][nt][i * 2 + 1] + bv.y);
                    __nv_bfloat16 h0 = __float2bfloat16(g0);
                    __nv_bfloat16 h1 = __float2bfloat16(g1);
                    __nv_bfloat16 l0 = __float2bfloat16(g0 - __bfloat162float(h0));
                    __nv_bfloat16 l1 = __float2bfloat16(g1 - __bfloat162float(h1));
                    *(__nv_bfloat162*)(g_hh + sl2 * HID + col) = __halves2bfloat162(h0, h1);
                    *(__nv_bfloat162*)(g_hl + sl2 * HID + col) = __halves2bfloat162(l0, l1);
                }
            }
        }
    }
}

__global__ __launch_bounds__(256, 2)
void gemm2_mma(const float* __restrict__ b2) {
    int tile = blockIdx.y;
    if (tile >= g_num_mtiles) return;
    int e = g_tile_e[tile], row0 = g_tile_r0[tile];
    int cnt = g_counts[e], off = g_offsets[e];
    int col0 = blockIdx.x * 128;
    extern __shared__ char sm[];
    uint32_t smb = smem_to_u32(sm);
    int tid = threadIdx.x, lane = tid & 31, wid = tid >> 5;
    int* s_row = (int*)sm;
    float* s_wgt = (float*)(sm + 512);
    if (tid < 128) {
        int sl = off + min(row0 + tid, max(cnt - 1, 0));
        s_row[tid] = sl;
        s_wgt[tid] = g_list_wgt[sl];
    }
    __syncthreads();

    const __nv_bfloat16* Bh = g_w2h + (size_t)e * HID * DIM;
    const __nv_bfloat16* Bl = g_w2l + (size_t)e * HID * DIM;

    auto load_chunk = [&](int c, int slot) {
        int ph = c >> 7;                 // 128 k-chunks per phase (HID/32)
        int kk = (c & 127) << 5;
        const __nv_bfloat16* As = (ph < 2) ? g_hh : g_hl;
        const __nv_bfloat16* Bs = (ph == 1) ? Bl : Bh;
        uint32_t ab = smb + 1024 + slot * STAGE_B;
        uint32_t bb = ab + ATILE_B;
#pragma unroll
        for (int i = 0; i < 2; i++) {
            int item = tid + (i << 8);
            int r = item >> 2, ch = item & 3;
            cpa16(ab + r * ASTRIDE + ch * 16,
                  (const char*)(As + (size_t)s_row[r] * HID + kk) + ch * 16);
        }
#pragma unroll
        for (int i = 0; i < 2; i++) {
            int item = tid + (i << 8);
            int r = item >> 4, ch = item & 15;
            cpa16(bb + r * BSTRIDE + ch * 16,
                  (const char*)(Bs + (size_t)(kk + r) * DIM + col0) + ch * 16);
        }
    };

    float acc[2][8][4];
#pragma unroll
    for (int a = 0; a < 2; a++)
#pragma unroll
        for (int b = 0; b < 8; b++)
#pragma unroll
            for (int q = 0; q < 4; q++) acc[a][b][q] = 0.0f;

    int m0 = (wid >> 1) * 32;
    int n0w = (wid & 1) * 64;
    uint32_t aoff = (uint32_t)((m0 + (lane & 15)) * ASTRIDE + (lane >> 4) * 16);
    uint32_t boff = (uint32_t)(((((lane >> 3) & 1) << 3) + (lane & 7)) * BSTRIDE +
                               (n0w + (lane >> 4) * 8) * 2);

    load_chunk(0, 0); CPA_COMMIT();
    load_chunk(1, 1); CPA_COMMIT();
    const int NCH = 384;                 // 3 phases x 128
    for (int c = 0; c < NCH; c++) {
        CPA_WAIT1();
        __syncthreads();
        int sl = c & 1;
        uint32_t ab = smb + 1024 + sl * STAGE_B;
        uint32_t bb = ab + ATILE_B;
#pragma unroll
        for (int ks = 0; ks < 2; ks++) {
            uint32_t a0[4], a1[4], bg[4][4];
            ldsm_x4(a0, ab + aoff + ks * 32);
            ldsm_x4(a1, ab + aoff + ks * 32 + 16 * ASTRIDE);
#pragma unroll
            for (int ng = 0; ng < 4; ng++)
                ldsm_x4_t(bg[ng], bb + boff + ks * 16 * BSTRIDE + ng * 32);
#pragma unroll
            for (int nt = 0; nt < 8; nt++) {
                uint32_t b0 = bg[nt >> 1][(nt & 1) * 2];
                uint32_t b1v = bg[nt >> 1][(nt & 1) * 2 + 1];
                mma16816(acc[0][nt], a0, b0, b1v);
                mma16816(acc[1][nt], a1, b0, b1v);
            }
        }
        __syncthreads();
        if (c + 2 < NCH) load_chunk(c + 2, sl);
        CPA_COMMIT();
    }

    int qr = lane >> 2, qc = (lane & 3) * 2;
#pragma unroll
    for (int mt = 0; mt < 2; mt++) {
#pragma unroll
        for (int i = 0; i < 2; i++) {
            int ml = m0 + mt * 16 + qr + i * 8;
            int r = row0 + ml;
            if (r < cnt) {
                size_t sl2 = (size_t)(off + r);
                float wgt = s_wgt[ml];
#pragma unroll
                for (int nt = 0; nt < 8; nt++) {
                    int col = col0 + n0w + nt * 8 + qc;
                    float2 bv = *(const float2*)(b2 + (size_t)e * DIM + col);
                    float y0 = wgt * (acc[mt][nt][i * 2 + 0] + bv.x);
                    float y1 = wgt * (acc[mt][nt][i * 2 + 1] + bv.y);
                    *(float2*)(g_y + sl2 * DIM + col) = make_float2(y0, y1);
                }
            }
        }
    }
}

// ===================== combine =====================
__global__ void combine_kernel(float* __restrict__ out) {
    int i = blockIdx.x * blockDim.x + threadIdx.x;
    if (i >= NTOK * DIM / 4) return;
    int t = i / (DIM / 4);
    int d4 = i % (DIM / 4);
    int s0 = g_slot_of[t * 2 + 0];
    int s1 = g_slot_of[t * 2 + 1];
    float4 a = ((const float4*)(g_y + (size_t)s0 * DIM))[d4];
    float4 b = ((const float4*)(g_y + (size_t)s1 * DIM))[d4];
    float4 o;
    o.x = a.x + b.x; o.y = a.y + b.y; o.z = a.z + b.z; o.w = a.w + b.w;
    ((float4*)out)[i] = o;
}

// ===================== launch =====================
extern "C" void kernel_launch(void* const* d_in, const int* in_sizes, int n_in,
                              void* d_out, int out_size) {
    const float* x  = (const float*)d_in[0];
    const float* gw = (const float*)d_in[1];
    const float* gb = (const float*)d_in[2];
    const float* w1 = (const float*)d_in[3];
    const float* b1 = (const float*)d_in[4];
    const float* w2 = (const float*)d_in[5];
    const float* b2 = (const float*)d_in[6];
    float* out = (float*)d_out;

    init_kernel<<<1, 32>>>();
    gate_kernel<<<NTOK / 8, 256>>>(x, gw, gb);
    prefix_kernel<<<1, 1>>>();
    scatter_kernel<<<NTOK / 256, 256>>>();

    size_t n4x = (size_t)NTOK * DIM / 4;
    size_t n4w = (size_t)NEXP * DIM * HID / 4;
    split_kernel<<<(unsigned)((n4x + 255) / 256), 256>>>(x,  0, n4x);
    split_kernel<<<(unsigned)((n4w + 255) / 256), 256>>>(w1, 1, n4w);
    split_kernel<<<(unsigned)((n4w + 255) / 256), 256>>>(w2, 2, n4w);

    gemm1_mma<<<dim3(HID / 128, MAXMT), 256, SMEM_BYTES>>>(b1);
    gemm2_mma<<<dim3(DIM / 128, MAXMT), 256, SMEM_BYTES>>>(b2);
    combine_kernel<<<(NTOK * DIM / 4 + 255) / 256, 256>>>(out);
}